// round 14
// baseline (speedup 1.0000x reference)
#include <cuda_runtime.h>
#include <cuda_fp16.h>
#include <cstdint>

// LinearAttentionCell with T=1 reduces algebraically to out = x @ Wv^T.
// R14: bulk-async W streaming. 11 structural variants all pinned at
// ~11.5-12.7us ~= 16MB W / 1.5TB/s with every pipe <45% -- the limiter is
// the per-thread LDG request path, not any execution resource. Fix:
// cp.async.bulk (sm_90 baseline PTX): one thread per CTA fires 128
// fire-and-forget 512B bulk copies of its W slice into fp32 smem against an
// mbarrier expect_tx; warps meanwhile convert x. No W LDG, no W STS, no
// scoreboard chains on the streaming path. NT=128 halves x L2 re-read
// traffic (16->8MB). Numerics: R13-validated single-product fp16
// (out ~= f16(x)*f16(w), fp32 acc, rel_err ~2.9e-4).

#define KDIM 2048
#define NDIM 2048
#define MDIM 64
#define NT   128
#define SPLITK 16
#define KCH  128
#define KSTEPS 8      // k16 steps per CTA
#define GT   256      // 8 warps: 2 wrow(m32) x 4 wcol(n32)

// dynamic smem layout (bytes)
#define SM_AH   0                       // [8 ksteps][2048] fp16 x tiles
#define SM_WF   16384                   // 128 rows x 132 floats (528B pitch)
#define SM_MBAR (SM_WF + 128 * 528)     // 83968
#define SM_TOTAL (SM_MBAR + 16)         // 83984
#define W_ROW_BYTES 512
#define W_PITCH_F 132                   // floats per smem W row (pad 4)

__device__ __forceinline__ uint32_t f16x2(float hi_e, float lo_e) {
    // packs: low 16 = f16(lo_e), high 16 = f16(hi_e)
    uint32_t r;
    asm("cvt.rn.f16x2.f32 %0, %1, %2;" : "=r"(r) : "f"(hi_e), "f"(lo_e));
    return r;
}

__device__ __forceinline__ void mma_f16(float* d, const uint32_t* a,
                                        uint32_t b0, uint32_t b1) {
    asm volatile(
        "mma.sync.aligned.m16n8k16.row.col.f32.f16.f16.f32 "
        "{%0,%1,%2,%3}, {%4,%5,%6,%7}, {%8,%9}, {%0,%1,%2,%3};"
        : "+f"(d[0]), "+f"(d[1]), "+f"(d[2]), "+f"(d[3])
        : "r"(a[0]), "r"(a[1]), "r"(a[2]), "r"(a[3]), "r"(b0), "r"(b1));
}

__device__ __forceinline__ void ldsm4(uint32_t* r, uint32_t addr) {
    asm volatile(
        "ldmatrix.sync.aligned.m8n8.x4.shared.b16 {%0,%1,%2,%3}, [%4];"
        : "=r"(r[0]), "=r"(r[1]), "=r"(r[2]), "=r"(r[3]) : "r"(addr));
}

__device__ __forceinline__ uint32_t smem_u32(const void* p) {
    return (uint32_t)__cvta_generic_to_shared(p);
}

#define MBAR_WAIT(mb, ph) do {                                                 \
    uint32_t _m = (mb); uint32_t _p = (ph); uint32_t _d;                       \
    asm volatile("{\n\t.reg .pred p;\n\t"                                      \
        "mbarrier.try_wait.parity.acquire.cta.shared::cta.b64 p, [%1], %2;\n\t"\
        "selp.b32 %0, 1, 0, p;\n\t}" : "=r"(_d) : "r"(_m), "r"(_p) : "memory");\
    if (!_d) {                                                                 \
        asm volatile("{\n\t.reg .pred P1;\n\t"                                 \
            "WL_%=:\n\t"                                                       \
            "mbarrier.try_wait.parity.acquire.cta.shared::cta.b64 P1, [%0], %1, 0x989680;\n\t" \
            "@P1 bra.uni WD_%=;\n\tbra.uni WL_%=;\n\tWD_%=:\n\t}"              \
            :: "r"(_m), "r"(_p) : "memory");                                   \
    }                                                                          \
} while (0)

__global__ __launch_bounds__(GT, 2)
void gemm_kernel(const float* __restrict__ x, const float* __restrict__ Wv,
                 float* __restrict__ out) {
    extern __shared__ __align__(16) char smem[];
    uint8_t* AH  = reinterpret_cast<uint8_t*>(smem + SM_AH);  // fp16 x tiles
    float*   WF  = reinterpret_cast<float*>(smem + SM_WF);    // fp32 W rows
    const uint32_t mbar = smem_u32(smem + SM_MBAR);

    const int tid  = threadIdx.x;
    const int lane = tid & 31;
    const int wid  = tid >> 5;
    const int wrow = wid >> 2;     // m32 group 0..1
    const int wcol = wid & 3;      // n32 group 0..3
    const int g  = lane >> 2;
    const int tt = lane & 3;

    const int n0 = blockIdx.x * NT;
    const int k0 = blockIdx.y * KCH;

    // ---- 1. mbarrier init ----
    if (tid == 0) {
        asm volatile("mbarrier.init.shared.b64 [%0], 1;" :: "r"(mbar) : "memory");
    }
    __syncthreads();

    // ---- 2. fire W bulk copies (one thread; fully async) ----
    if (tid == 0) {
        asm volatile("mbarrier.arrive.expect_tx.shared.b64 _, [%0], %1;"
                     :: "r"(mbar), "r"(NT * W_ROW_BYTES) : "memory");
        const float* wsrc = Wv + (size_t)n0 * KDIM + k0;
        uint32_t wdst = smem_u32(WF);
#pragma unroll 4
        for (int rr = 0; rr < NT; rr++) {
            asm volatile(
                "cp.async.bulk.shared::cluster.global.mbarrier::complete_tx::bytes "
                "[%0], [%1], %2, [%3];"
                :: "r"(wdst + rr * (W_PITCH_F * 4)),
                   "l"(wsrc + (size_t)rr * KDIM),
                   "r"(W_ROW_BYTES), "r"(mbar)
                : "memory");
        }
    }

    // ---- 3. meanwhile: x slice -> fp16 A tiles (R13-validated path) ----
    const int r   = tid >> 2;           // 0..63
    const int kq  = (tid & 3) * 4;
    const int hq  = kq >> 3;
    const int off8 = (kq & 4) ? 8 : 0;
    const int sts_off = r * 32 + (((hq ^ (r >> 2)) & 1) << 4) + off8;
    {
        const float* xp = x + (size_t)r * KDIM + k0 + kq;
        float4 xr[KSTEPS];
#pragma unroll
        for (int i = 0; i < KSTEPS; i++)
            xr[i] = *reinterpret_cast<const float4*>(xp + i * 16);
#pragma unroll
        for (int i = 0; i < KSTEPS; i++) {
            uint32_t h01 = f16x2(xr[i].y, xr[i].x);
            uint32_t h23 = f16x2(xr[i].w, xr[i].z);
            *reinterpret_cast<uint2*>(&AH[i * 2048 + sts_off]) = make_uint2(h01, h23);
        }
    }
    __syncthreads();              // A tiles visible
    MBAR_WAIT(mbar, 0);           // W smem ready

    // ---- 4. MMA sweep ----
    const int am0 = (wrow * 2 + 0) * 16 + (lane & 15);
    const int am1 = am0 + 16;
    const int akh = lane >> 4;
    const uint32_t aoff0 = am0 * 32 + (((akh ^ (am0 >> 2)) & 1) << 4);
    const uint32_t aoff1 = am1 * 32 + (((akh ^ (am1 >> 2)) & 1) << 4);
    const uint32_t ah_base = smem_u32(AH);

    float acc[2][4][4];
#pragma unroll
    for (int a = 0; a < 2; a++)
#pragma unroll
        for (int b = 0; b < 4; b++)
#pragma unroll
            for (int c = 0; c < 4; c++) acc[a][b][c] = 0.f;

    // B row base indices (fp32 smem, pitch 132 floats; conflict-light)
    int browf[4];
#pragma unroll
    for (int nf = 0; nf < 4; nf++)
        browf[nf] = (wcol * 32 + nf * 8 + g) * W_PITCH_F + 2 * tt;

#pragma unroll
    for (int ks = 0; ks < KSTEPS; ks++) {
        uint32_t a0[4], a1[4];
        ldsm4(a0, ah_base + ks * 2048 + aoff0);
        ldsm4(a1, ah_base + ks * 2048 + aoff1);

#pragma unroll
        for (int nf = 0; nf < 4; nf++) {
            float2 p = *reinterpret_cast<const float2*>(&WF[browf[nf] + ks * 16]);
            float2 q = *reinterpret_cast<const float2*>(&WF[browf[nf] + ks * 16 + 8]);
            uint32_t b0 = f16x2(p.y, p.x);
            uint32_t b1 = f16x2(q.y, q.x);
            mma_f16(acc[0][nf], a0, b0, b1);
            mma_f16(acc[1][nf], a1, b0, b1);
        }
    }

    // ---- 5. epilogue: split-K via vector atomics ----
#pragma unroll
    for (int mb = 0; mb < 2; mb++) {
#pragma unroll
        for (int nf = 0; nf < 4; nf++) {
            int m = (wrow * 2 + mb) * 16 + g;
            int n = n0 + wcol * 32 + nf * 8 + 2 * tt;
            atomicAdd(reinterpret_cast<float2*>(&out[m * NDIM + n]),
                      make_float2(acc[mb][nf][0], acc[mb][nf][1]));
            atomicAdd(reinterpret_cast<float2*>(&out[(m + 8) * NDIM + n]),
                      make_float2(acc[mb][nf][2], acc[mb][nf][3]));
        }
    }
}

extern "C" void kernel_launch(void* const* d_in, const int* in_sizes, int n_in,
                              void* d_out, int out_size) {
    // inputs: 0=x [64,1,2048] f32, 1=Wq, 2=bq, 3=Wk, 4=bk, 5=Wv [2048,2048], 6=pos
    const float* x  = (const float*)d_in[0];
    const float* Wv = (const float*)d_in[5];
    float* out = (float*)d_out;

    cudaFuncSetAttribute(gemm_kernel,
                         cudaFuncAttributeMaxDynamicSharedMemorySize, SM_TOTAL);

    cudaMemsetAsync(out, 0, (size_t)MDIM * NDIM * sizeof(float));
    dim3 grid(NDIM / NT, SPLITK);   // 16 x 16 = 256 CTAs
    gemm_kernel<<<grid, GT, SM_TOTAL>>>(x, Wv, out);

    (void)in_sizes; (void)n_in; (void)out_size;
}

// round 15
// speedup vs baseline: 1.1572x; 1.1572x over previous
#include <cuda_runtime.h>
#include <cuda_fp16.h>
#include <cstdint>

// LinearAttentionCell with T=1 reduces algebraically to out = x @ Wv^T.
// R15: traffic-minimized single-product fp16 GEMM (R13 numerics,
// rel_err ~2.9e-4). Evidence through R14: delivered bandwidth is capped at
// ~1.45 TB/s regardless of request mechanism/MLP/occupancy -> the only
// remaining lever is total bytes on the fabric. NT=128 halves x-fragment
// L2 re-reads (16 MB -> 8 MB; W 16 MB is irreducible fp32).
// Grid 16x16=256 CTAs, all resident (2/SM, 48 KB smem). Burst LDG loads,
// one barrier, 4 ldsm + 8 MMA per kstep, atomic split-K epilogue.

#define KDIM 2048
#define NDIM 2048
#define MDIM 64
#define NT   128
#define SPLITK 16
#define KCH  128
#define KSTEPS 8      // k16 steps per CTA
#define GT   256      // 8 warps: 2 wm(m32) x 4 wn(n32)

__device__ __forceinline__ uint32_t f16x2(float hi_e, float lo_e) {
    // packs: low 16 = f16(lo_e), high 16 = f16(hi_e)
    uint32_t r;
    asm("cvt.rn.f16x2.f32 %0, %1, %2;" : "=r"(r) : "f"(hi_e), "f"(lo_e));
    return r;
}

__device__ __forceinline__ void mma_f16(float* d, const uint32_t* a,
                                        uint32_t b0, uint32_t b1) {
    asm volatile(
        "mma.sync.aligned.m16n8k16.row.col.f32.f16.f16.f32 "
        "{%0,%1,%2,%3}, {%4,%5,%6,%7}, {%8,%9}, {%0,%1,%2,%3};"
        : "+f"(d[0]), "+f"(d[1]), "+f"(d[2]), "+f"(d[3])
        : "r"(a[0]), "r"(a[1]), "r"(a[2]), "r"(a[3]), "r"(b0), "r"(b1));
}

__device__ __forceinline__ void ldsm4(uint32_t* r, uint32_t addr) {
    asm volatile(
        "ldmatrix.sync.aligned.m8n8.x4.shared.b16 {%0,%1,%2,%3}, [%4];"
        : "=r"(r[0]), "=r"(r[1]), "=r"(r[2]), "=r"(r[3]) : "r"(addr));
}

// swizzled 16B-chunk offset within a [rows x 16k] fp16 tile (pitch 32B)
__device__ __forceinline__ uint32_t swz(int row, int khalf) {
    return (uint32_t)(row * 32 + (((khalf ^ (row >> 2)) & 1) << 4));
}

__global__ __launch_bounds__(GT, 2)
void gemm_kernel(const float* __restrict__ x, const float* __restrict__ Wv,
                 float* __restrict__ out) {
    __shared__ __align__(16) uint8_t AH[KSTEPS][2048];   // x fp16 [64r x 16k]
    __shared__ __align__(16) uint8_t WH[KSTEPS][4096];   // w fp16 [128r x 16k]

    const int tid  = threadIdx.x;
    const int lane = tid & 31;
    const int wid  = tid >> 5;
    const int wm   = wid & 1;      // m32 group 0..1
    const int wn   = wid >> 1;     // n32 group 0..3
    const int g  = lane >> 2;
    const int tt = lane & 3;

    const int n0 = blockIdx.x * NT;
    const int k0 = blockIdx.y * KCH;

    // ---- ingress mapping: thread -> (row r, 4-float chunk kq) ----
    const int r   = tid >> 2;           // 0..63
    const int kq  = (tid & 3) * 4;      // 0,4,8,12
    const int hq  = kq >> 3;
    const int off8 = (kq & 4) ? 8 : 0;
    const uint32_t so_x  = swz(r, hq) + off8;        // x rows 0..63
    const uint32_t so_w0 = swz(r, hq) + off8;        // W rows 0..63
    const uint32_t so_w1 = swz(r + 64, hq) + off8;   // W rows 64..127

    const float* xp  = x  + (size_t)r * KDIM + k0 + kq;
    const float* wp0 = Wv + (size_t)(n0 + r) * KDIM + k0 + kq;
    const float* wp1 = Wv + (size_t)(n0 + r + 64) * KDIM + k0 + kq;

    // ---- burst 1: x (8) + W rows r (8) in flight together ----
    {
        float4 xr[KSTEPS], wr[KSTEPS];
#pragma unroll
        for (int i = 0; i < KSTEPS; i++)
            xr[i] = *reinterpret_cast<const float4*>(xp + i * 16);
#pragma unroll
        for (int i = 0; i < KSTEPS; i++)
            wr[i] = *reinterpret_cast<const float4*>(wp0 + i * 16);
#pragma unroll
        for (int i = 0; i < KSTEPS; i++) {
            uint32_t h01 = f16x2(xr[i].y, xr[i].x);
            uint32_t h23 = f16x2(xr[i].w, xr[i].z);
            *reinterpret_cast<uint2*>(&AH[i][so_x]) = make_uint2(h01, h23);
        }
#pragma unroll
        for (int i = 0; i < KSTEPS; i++) {
            uint32_t h01 = f16x2(wr[i].y, wr[i].x);
            uint32_t h23 = f16x2(wr[i].w, wr[i].z);
            *reinterpret_cast<uint2*>(&WH[i][so_w0]) = make_uint2(h01, h23);
        }
    }
    // ---- burst 2: W rows r+64 ----
    {
        float4 wr[KSTEPS];
#pragma unroll
        for (int i = 0; i < KSTEPS; i++)
            wr[i] = *reinterpret_cast<const float4*>(wp1 + i * 16);
#pragma unroll
        for (int i = 0; i < KSTEPS; i++) {
            uint32_t h01 = f16x2(wr[i].y, wr[i].x);
            uint32_t h23 = f16x2(wr[i].w, wr[i].z);
            *reinterpret_cast<uint2*>(&WH[i][so_w1]) = make_uint2(h01, h23);
        }
    }

    __syncthreads();   // the only barrier

    // ---- ldmatrix lane offsets ----
    const int am0 = wm * 32 + (lane & 15);
    const int am1 = am0 + 16;
    const int akh = lane >> 4;
    const uint32_t aoff0 = swz(am0, (akh ^ 0) & 1) - ((((am0 >> 2) ^ akh) & 1) << 4)
                         + ((((akh) ^ (am0 >> 2)) & 1) << 4);  // = swz(am0, akh)
    const uint32_t aoff1 = swz(am1, akh);
    const uint32_t aoffA = swz(am0, akh);
    // B: two n16 tiles per warp at rows wn*32 and wn*32+16
    const int nl  = ((lane >> 4) & 1) * 8 + (lane & 7);
    const int bkh = (lane >> 3) & 1;
    const int br0 = wn * 32 + nl;
    const int br1 = wn * 32 + 16 + nl;
    const uint32_t boff0 = swz(br0, bkh);
    const uint32_t boff1 = swz(br1, bkh);

    float acc[2][4][4];
#pragma unroll
    for (int a = 0; a < 2; a++)
#pragma unroll
        for (int b = 0; b < 4; b++)
#pragma unroll
            for (int c = 0; c < 4; c++) acc[a][b][c] = 0.f;

#pragma unroll
    for (int ks = 0; ks < KSTEPS; ks++) {
        uint32_t a0[4], a1[4], b0[4], b1[4];
        const uint32_t ahb = (uint32_t)__cvta_generic_to_shared(&AH[ks][0]);
        const uint32_t whb = (uint32_t)__cvta_generic_to_shared(&WH[ks][0]);
        ldsm4(a0, ahb + aoffA);
        ldsm4(a1, ahb + aoff1);
        ldsm4(b0, whb + boff0);
        ldsm4(b1, whb + boff1);

        mma_f16(acc[0][0], a0, b0[0], b0[1]);
        mma_f16(acc[0][1], a0, b0[2], b0[3]);
        mma_f16(acc[1][0], a1, b0[0], b0[1]);
        mma_f16(acc[1][1], a1, b0[2], b0[3]);
        mma_f16(acc[0][2], a0, b1[0], b1[1]);
        mma_f16(acc[0][3], a0, b1[2], b1[3]);
        mma_f16(acc[1][2], a1, b1[0], b1[1]);
        mma_f16(acc[1][3], a1, b1[2], b1[3]);
    }
    (void)aoff0;

    // ---- epilogue: split-K via vector atomics ----
#pragma unroll
    for (int mb = 0; mb < 2; mb++) {
#pragma unroll
        for (int nf = 0; nf < 4; nf++) {
            int m = wm * 32 + mb * 16 + g;
            int n = n0 + wn * 32 + nf * 8 + 2 * tt;
            atomicAdd(reinterpret_cast<float2*>(&out[m * NDIM + n]),
                      make_float2(acc[mb][nf][0], acc[mb][nf][1]));
            atomicAdd(reinterpret_cast<float2*>(&out[(m + 8) * NDIM + n]),
                      make_float2(acc[mb][nf][2], acc[mb][nf][3]));
        }
    }
}

extern "C" void kernel_launch(void* const* d_in, const int* in_sizes, int n_in,
                              void* d_out, int out_size) {
    // inputs: 0=x [64,1,2048] f32, 1=Wq, 2=bq, 3=Wk, 4=bk, 5=Wv [2048,2048], 6=pos
    const float* x  = (const float*)d_in[0];
    const float* Wv = (const float*)d_in[5];
    float* out = (float*)d_out;

    cudaMemsetAsync(out, 0, (size_t)MDIM * NDIM * sizeof(float));
    dim3 grid(NDIM / NT, SPLITK);   // 16 x 16 = 256 CTAs, all resident
    gemm_kernel<<<grid, GT>>>(x, Wv, out);

    (void)in_sizes; (void)n_in; (void)out_size;
}